// round 7
// baseline (speedup 1.0000x reference)
#include <cuda_runtime.h>
#include <math.h>

#define UNITS   512
#define ORDER   256
#define TSTEPS  1024
#define BATCH   64

#define NCTA     128
#define NTHREADS 256
#define GROUPS   8
#define CPG      16   // CTAs per group
#define BPG      8    // batches per group
#define JH       32   // h columns per CTA
#define JM       16   // m columns per CTA

#define WHK_STRIDE 516
#define WMK_STRIDE 260
#define WAT_STRIDE 260

// ---- shared memory layout (in floats) ----
#define WHK_OFF  0
#define WMK_OFF  (WHK_OFF + JH*WHK_STRIDE)     // 16512
#define WAT_OFF  (WMK_OFF + JH*WMK_STRIDE)     // 24832
#define HS_OFF   (WAT_OFF + JM*WAT_STRIDE)     // 28992  (8 x 512)
#define MS_OFF   (HS_OFF + BPG*UNITS)          // 33088  (8 x 256)
#define IK_OFF   (MS_OFF + BPG*ORDER)          // 35136
#define BTMK_OFF (IK_OFF + JH)
#define HE_OFF   (BTMK_OFF + JH)
#define BT_OFF   (HE_OFF + JH)
#define ME_OFF   (BT_OFF + JM)
#define XV_OFF   (ME_OFF + JM)
#define US_OFF   (XV_OFF + BPG)
#define HEP_OFF  (US_OFF + BPG)
#define MEP_OFF  (HEP_OFF + BPG)
#define IE_OFF   (MEP_OFF + BPG)
#define SMEM_FLOATS (IE_OFF + 4)
#define SMEM_BYTES  (SMEM_FLOATS * 4)

// ---- device scratch (no allocations allowed) ----
__device__ float d_MK2[ORDER * UNITS];                    // mk + AT@mk
__device__ float d_BTmk[UNITS];                           // BT@mk
__device__ float d_hbuf[2][BATCH * UNITS];                // double-buffered h state
__device__ float d_mbuf[2][BATCH * ORDER];                // double-buffered m state
__device__ float d_upart[(TSTEPS + 1) * BATCH * CPG];     // per-CTA partials of h.he + m.me
__device__ unsigned int d_bar_count[GROUPS];
__device__ volatile unsigned int d_bar_gen[GROUPS];

typedef unsigned long long u64;

__device__ __forceinline__ void fma2(u64 &acc, u64 a, u64 b) {
    asm("fma.rn.f32x2 %0, %1, %2, %0;" : "+l"(acc) : "l"(a), "l"(b));
}
__device__ __forceinline__ float red2(u64 v) {
    float lo, hi;
    asm("mov.b64 {%0, %1}, %2;" : "=f"(lo), "=f"(hi) : "l"(v));
    return lo + hi;
}

// ===================== setup: fold matrices, zero state, reset barriers =====================
__global__ void lmu_setup_kernel(const float* __restrict__ mk,
                                 const float* __restrict__ AT,
                                 const float* __restrict__ BT) {
    int blk = blockIdx.x, tid = threadIdx.x;
    if (blk < 512) {
        // MK2[k][j] = mk[k][j] + sum_q AT[k][q] * mk[q][j]
        int e = blk * 256 + tid;           // 0 .. 131071
        int k = e >> 9, j = e & 511;
        float acc = mk[k * UNITS + j];
        const float* atrow = AT + k * ORDER;
        #pragma unroll 4
        for (int q = 0; q < ORDER; ++q) acc += atrow[q] * mk[q * UNITS + j];
        d_MK2[e] = acc;
    } else if (blk == 512) {
        for (int j = tid; j < UNITS; j += 256) {
            float acc = 0.f;
            #pragma unroll 4
            for (int q = 0; q < ORDER; ++q) acc += BT[q] * mk[q * UNITS + j];
            d_BTmk[j] = acc;
        }
    } else if (blk <= 518) {
        int base = (blk - 513) * 256 + tid;   // 6 blocks x 256 = 1536 threads
        for (int i = base; i < BATCH * UNITS; i += 6 * 256) d_hbuf[0][i] = 0.f;
        for (int i = base; i < BATCH * ORDER; i += 6 * 256) d_mbuf[0][i] = 0.f;
    } else {
        if (tid < GROUPS) { d_bar_count[tid] = 0; d_bar_gen[tid] = 0; }
    }
}

// ===================== main persistent kernel =====================
extern __shared__ float smem[];

__global__ void __launch_bounds__(NTHREADS, 1)
lmu_main_kernel(const float* __restrict__ x,    // [64,1024,1]
                const float* __restrict__ ie,   // [1,1]
                const float* __restrict__ he,   // [512,1]
                const float* __restrict__ me,   // [256,1]
                const float* __restrict__ ik,   // [1,512]
                const float* __restrict__ hk,   // [512,512]
                const float* __restrict__ AT,   // [256,256]
                const float* __restrict__ BT,   // [1,256]
                float* __restrict__ out)        // [64,1024,512]
{
    const int tid = threadIdx.x;
    const int g   = blockIdx.x >> 4;     // group 0..7
    const int cg  = blockIdx.x & 15;     // CTA within group 0..15
    const int b0  = g * BPG;
    const int jh0 = cg * JH;
    const int jm0 = cg * JM;

    // ---- one-time: load weight slices into SMEM (transposed, padded) ----
    for (int i = tid; i < JH * UNITS; i += NTHREADS) {          // whk[j][k] = hk[k][jh0+j]
        int k = i >> 5, j = i & 31;
        smem[WHK_OFF + j * WHK_STRIDE + k] = hk[k * UNITS + jh0 + j];
    }
    for (int i = tid; i < JH * ORDER; i += NTHREADS) {          // wmk[j][k] = MK2[k][jh0+j]
        int k = i >> 5, j = i & 31;
        smem[WMK_OFF + j * WMK_STRIDE + k] = d_MK2[k * UNITS + jh0 + j];
    }
    for (int i = tid; i < JM * ORDER; i += NTHREADS) {          // wat[o][k] = AT[k][jm0+o]
        int k = i >> 4, o = i & 15;
        smem[WAT_OFF + o * WAT_STRIDE + k] = AT[k * ORDER + jm0 + o];
    }
    if (tid < JH) {
        smem[IK_OFF + tid]   = ik[jh0 + tid];
        smem[BTMK_OFF + tid] = d_BTmk[jh0 + tid];
        smem[HE_OFF + tid]   = he[jh0 + tid];
    }
    if (tid < JM) {
        smem[BT_OFF + tid] = BT[jm0 + tid];
        smem[ME_OFF + tid] = me[jm0 + tid];
    }
    if (tid == 0) smem[IE_OFF] = ie[0];
    __syncthreads();

    const int bh = tid >> 5, jj = tid & 31;   // h-job mapping (8 warps x 32 cols)
    const int bm = tid >> 4, oo = tid & 15;   // m-job mapping (threads 0..127)

    for (int t = 0; t < TSTEPS; ++t) {
        const int p = t & 1;

        // ---- stage A: fetch states from global (L2-coherent) into SMEM ----
        {
            const float4* hs = reinterpret_cast<const float4*>(d_hbuf[p] + b0 * UNITS);
            float4*       hd = reinterpret_cast<float4*>(smem + HS_OFF);
            #pragma unroll
            for (int i = tid; i < (BPG * UNITS) / 4; i += NTHREADS) hd[i] = __ldcg(hs + i);
            const float4* ms = reinterpret_cast<const float4*>(d_mbuf[p] + b0 * ORDER);
            float4*       md = reinterpret_cast<float4*>(smem + MS_OFF);
            #pragma unroll
            for (int i = tid; i < (BPG * ORDER) / 4; i += NTHREADS) md[i] = __ldcg(ms + i);
            if (tid < BPG) {
                float xv = x[(b0 + tid) * TSTEPS + t];
                float u  = xv * smem[IE_OFF];
                if (t > 0) {
                    const float* up = d_upart + ((size_t)t * BATCH + b0 + tid) * CPG;
                    #pragma unroll
                    for (int c = 0; c < CPG; ++c) u += __ldcg(up + c);
                }
                smem[XV_OFF + tid] = xv;
                smem[US_OFF + tid] = u;
            }
        }
        __syncthreads();

        // ---- stage B1: h update (every thread computes one h output) ----
        {
            const float* wrow = smem + WHK_OFF + jj * WHK_STRIDE;
            const float* hrow = smem + HS_OFF + bh * UNITS;
            u64 a0 = 0, a1 = 0, a2 = 0, a3 = 0;
            #pragma unroll 4
            for (int k = 0; k < UNITS; k += 8) {
                ulonglong2 w0 = *reinterpret_cast<const ulonglong2*>(wrow + k);
                ulonglong2 h0 = *reinterpret_cast<const ulonglong2*>(hrow + k);
                ulonglong2 w1 = *reinterpret_cast<const ulonglong2*>(wrow + k + 4);
                ulonglong2 h1 = *reinterpret_cast<const ulonglong2*>(hrow + k + 4);
                fma2(a0, w0.x, h0.x); fma2(a1, w0.y, h0.y);
                fma2(a2, w1.x, h1.x); fma2(a3, w1.y, h1.y);
            }
            const float* w2row = smem + WMK_OFF + jj * WMK_STRIDE;
            const float* mrow  = smem + MS_OFF + bh * ORDER;
            #pragma unroll 4
            for (int k = 0; k < ORDER; k += 8) {
                ulonglong2 w0 = *reinterpret_cast<const ulonglong2*>(w2row + k);
                ulonglong2 m0 = *reinterpret_cast<const ulonglong2*>(mrow + k);
                ulonglong2 w1 = *reinterpret_cast<const ulonglong2*>(w2row + k + 4);
                ulonglong2 m1 = *reinterpret_cast<const ulonglong2*>(mrow + k + 4);
                fma2(a0, w0.x, m0.x); fma2(a1, w0.y, m0.y);
                fma2(a2, w1.x, m1.x); fma2(a3, w1.y, m1.y);
            }
            float val = (red2(a0) + red2(a1)) + (red2(a2) + red2(a3));
            val += smem[XV_OFF + bh] * smem[IK_OFF + jj];
            val += smem[US_OFF + bh] * smem[BTMK_OFF + jj];
            float hv = tanhf(val);
            out[((size_t)(b0 + bh) * TSTEPS + t) * UNITS + jh0 + jj] = hv;
            __stcg(&d_hbuf[p ^ 1][(b0 + bh) * UNITS + jh0 + jj], hv);
            // deterministic warp reduction of he contribution
            float hw = smem[HE_OFF + jj] * hv;
            hw += __shfl_down_sync(0xffffffffu, hw, 16);
            hw += __shfl_down_sync(0xffffffffu, hw, 8);
            hw += __shfl_down_sync(0xffffffffu, hw, 4);
            hw += __shfl_down_sync(0xffffffffu, hw, 2);
            hw += __shfl_down_sync(0xffffffffu, hw, 1);
            if (jj == 0) smem[HEP_OFF + bh] = hw;
        }

        // ---- stage B2: m update (threads 0..127, warps 0-3, one m output each) ----
        if (tid < 128) {
            const float* arow = smem + WAT_OFF + oo * WAT_STRIDE;
            const float* mrow = smem + MS_OFF + bm * ORDER;
            u64 c0 = 0, c1 = 0, c2 = 0, c3 = 0;
            #pragma unroll 4
            for (int k = 0; k < ORDER; k += 8) {
                ulonglong2 w0 = *reinterpret_cast<const ulonglong2*>(arow + k);
                ulonglong2 m0 = *reinterpret_cast<const ulonglong2*>(mrow + k);
                ulonglong2 w1 = *reinterpret_cast<const ulonglong2*>(arow + k + 4);
                ulonglong2 m1 = *reinterpret_cast<const ulonglong2*>(mrow + k + 4);
                fma2(c0, w0.x, m0.x); fma2(c1, w0.y, m0.y);
                fma2(c2, w1.x, m1.x); fma2(c3, w1.y, m1.y);
            }
            float dot  = (red2(c0) + red2(c1)) + (red2(c2) + red2(c3));
            float mnew = mrow[jm0 + oo] + dot + smem[US_OFF + bm] * smem[BT_OFF + oo];
            __stcg(&d_mbuf[p ^ 1][(b0 + bm) * ORDER + jm0 + oo], mnew);
            // deterministic half-warp reduction of me contribution
            float mw = smem[ME_OFF + oo] * mnew;
            mw += __shfl_down_sync(0xffffffffu, mw, 8, 16);
            mw += __shfl_down_sync(0xffffffffu, mw, 4, 16);
            mw += __shfl_down_sync(0xffffffffu, mw, 2, 16);
            mw += __shfl_down_sync(0xffffffffu, mw, 1, 16);
            if (oo == 0) smem[MEP_OFF + bm] = mw;
        }
        __syncthreads();

        // ---- write u partial for step t+1 (deterministic per-CTA slot) ----
        if (tid < BPG)
            d_upart[((size_t)(t + 1) * BATCH + b0 + tid) * CPG + cg] =
                smem[HEP_OFF + tid] + smem[MEP_OFF + tid];

        __threadfence();      // all this thread's global writes visible device-wide
        __syncthreads();

        // ---- group barrier (16 co-resident CTAs, sense via generation counter) ----
        if (tid == 0) {
            unsigned target = (unsigned)(t + 1);
            if (atomicAdd(&d_bar_count[g], 1u) == CPG - 1) {
                d_bar_count[g] = 0;
                __threadfence();
                d_bar_gen[g] = target;
            } else {
                while (d_bar_gen[g] < target) { }
            }
            __threadfence();
        }
        __syncthreads();
    }
}

// ===================== launch =====================
extern "C" void kernel_launch(void* const* d_in, const int* in_sizes, int n_in,
                              void* d_out, int out_size) {
    const float* x  = (const float*)d_in[0];
    const float* ie = (const float*)d_in[1];
    const float* he = (const float*)d_in[2];
    const float* me = (const float*)d_in[3];
    const float* ik = (const float*)d_in[4];
    const float* hk = (const float*)d_in[5];
    const float* mk = (const float*)d_in[6];
    const float* AT = (const float*)d_in[7];
    const float* BT = (const float*)d_in[8];
    float* out = (float*)d_out;

    cudaFuncSetAttribute(lmu_main_kernel,
                         cudaFuncAttributeMaxDynamicSharedMemorySize, SMEM_BYTES);

    lmu_setup_kernel<<<520, 256>>>(mk, AT, BT);
    lmu_main_kernel<<<NCTA, NTHREADS, SMEM_BYTES>>>(x, ie, he, me, ik, hk, AT, BT, out);
}

// round 10
// speedup vs baseline: 1.4737x; 1.4737x over previous
#include <cuda_runtime.h>
#include <math.h>

#define UNITS   512
#define ORDER   256
#define TSTEPS  1024
#define BATCH   64

#define NCTA     128
#define NTHREADS 256
#define GROUPS   8
#define CPG      16   // CTAs per group
#define BPG      8    // batches per group
#define JH       32   // h columns per CTA
#define JM       16   // m columns per CTA

// ---- shared memory layout (float offsets) ----
#define WHK_OFF   0        // [128 kc][32 col] float4 = 16384 f
#define WMK_OFF   16384    // [64 kc][32 col] float4 =  8192 f
#define WAT_OFF   24576    // [64 kc][16 col] float4 =  4096 f
#define HS_OFF    28672    // 8 rows, stride 129 float4 (516 floats)
#define MS_OFF    32800    // 8 rows, stride 65 float4 (260 floats)
#define XS_OFF    34880    // [8][1024]
#define PH_OFF    43072    // [4][8][33]
#define PM_OFF    44128    // [4][8][17]
#define IK_OFF    44672
#define BTMK_OFF  44704
#define HE_OFF    44736
#define BT_OFF    44768
#define ME_OFF    44784
#define US_OFF    44800
#define HEP_OFF   44808
#define MEP_OFF   44816
#define IE_OFF    44824
#define SMEM_FLOATS 44828
#define SMEM_BYTES  (SMEM_FLOATS * 4)

// ---- device scratch ----
__device__ float d_MK2[ORDER * UNITS];                 // mk + AT@mk
__device__ float d_BTmk[UNITS];                        // BT@mk
__device__ float d_hbuf[2][BATCH * UNITS];             // double-buffered h state
__device__ float d_mbuf[2][BATCH * ORDER];             // double-buffered m state
__device__ float d_upart[(TSTEPS + 1) * BATCH * CPG];  // per-CTA partials of h.he + m.me
__device__ unsigned int d_bar_count[GROUPS];
__device__ volatile unsigned int d_bar_gen[GROUPS];

typedef unsigned long long u64;

__device__ __forceinline__ void fma2(u64 &acc, u64 a, u64 b) {
    asm("fma.rn.f32x2 %0, %1, %2, %0;" : "+l"(acc) : "l"(a), "l"(b));
}
__device__ __forceinline__ float red2(u64 v) {
    float lo, hi;
    asm("mov.b64 {%0, %1}, %2;" : "=f"(lo), "=f"(hi) : "l"(v));
    return lo + hi;
}

// ===================== setup =====================
__global__ void lmu_setup_kernel(const float* __restrict__ mk,
                                 const float* __restrict__ AT,
                                 const float* __restrict__ BT) {
    int blk = blockIdx.x, tid = threadIdx.x;
    if (blk < 512) {
        int e = blk * 256 + tid;
        int k = e >> 9, j = e & 511;
        float acc = mk[k * UNITS + j];
        const float* atrow = AT + k * ORDER;
        #pragma unroll 4
        for (int q = 0; q < ORDER; ++q) acc += atrow[q] * mk[q * UNITS + j];
        d_MK2[e] = acc;
    } else if (blk == 512) {
        for (int j = tid; j < UNITS; j += 256) {
            float acc = 0.f;
            #pragma unroll 4
            for (int q = 0; q < ORDER; ++q) acc += BT[q] * mk[q * UNITS + j];
            d_BTmk[j] = acc;
        }
    } else if (blk <= 518) {
        int base = (blk - 513) * 256 + tid;
        for (int i = base; i < BATCH * UNITS; i += 6 * 256) d_hbuf[0][i] = 0.f;
        for (int i = base; i < BATCH * ORDER; i += 6 * 256) d_mbuf[0][i] = 0.f;
    } else {
        if (tid < GROUPS) { d_bar_count[tid] = 0; d_bar_gen[tid] = 0; }
    }
}

// ===================== main persistent kernel =====================
extern __shared__ float smem[];

__global__ void __launch_bounds__(NTHREADS, 1)
lmu_main_kernel(const float* __restrict__ x,    // [64,1024,1]
                const float* __restrict__ ie,   // [1,1]
                const float* __restrict__ he,   // [512,1]
                const float* __restrict__ me,   // [256,1]
                const float* __restrict__ ik,   // [1,512]
                const float* __restrict__ hk,   // [512,512]
                const float* __restrict__ AT,   // [256,256]
                const float* __restrict__ BT,   // [1,256]
                float* __restrict__ out)        // [64,1024,512]
{
    const int tid = threadIdx.x;
    const int g   = blockIdx.x >> 4;     // group 0..7
    const int cg  = blockIdx.x & 15;     // CTA within group
    const int b0  = g * BPG;
    const int jh0 = cg * JH;
    const int jm0 = cg * JM;

    float4*       HS4w  = reinterpret_cast<float4*>(smem + HS_OFF);
    float4*       MS4w  = reinterpret_cast<float4*>(smem + MS_OFF);
    const float4* WHK4  = reinterpret_cast<const float4*>(smem + WHK_OFF);
    const float4* WMK4  = reinterpret_cast<const float4*>(smem + WMK_OFF);
    const float4* WAT4  = reinterpret_cast<const float4*>(smem + WAT_OFF);

    // ---- one-time weight preload (transposed into [kc][col] float4 tiles) ----
    {
        float4* w = reinterpret_cast<float4*>(smem + WHK_OFF);
        for (int idx = tid; idx < 128 * 32; idx += NTHREADS) {
            int kc = idx >> 5, col = idx & 31;
            int k = kc * 4, j = jh0 + col;
            w[idx] = make_float4(hk[(k+0)*UNITS + j], hk[(k+1)*UNITS + j],
                                 hk[(k+2)*UNITS + j], hk[(k+3)*UNITS + j]);
        }
        float4* w2 = reinterpret_cast<float4*>(smem + WMK_OFF);
        for (int idx = tid; idx < 64 * 32; idx += NTHREADS) {
            int kc = idx >> 5, col = idx & 31;
            int k = kc * 4, j = jh0 + col;
            w2[idx] = make_float4(d_MK2[(k+0)*UNITS + j], d_MK2[(k+1)*UNITS + j],
                                  d_MK2[(k+2)*UNITS + j], d_MK2[(k+3)*UNITS + j]);
        }
        float4* w3 = reinterpret_cast<float4*>(smem + WAT_OFF);
        for (int idx = tid; idx < 64 * 16; idx += NTHREADS) {
            int kc = idx >> 4, col = idx & 15;
            int k = kc * 4, j = jm0 + col;
            w3[idx] = make_float4(AT[(k+0)*ORDER + j], AT[(k+1)*ORDER + j],
                                  AT[(k+2)*ORDER + j], AT[(k+3)*ORDER + j]);
        }
        // x preload: xs[b][t]
        for (int i = tid; i < BPG * TSTEPS; i += NTHREADS) {
            int b = i >> 10, t = i & 1023;
            smem[XS_OFF + i] = x[(b0 + b) * TSTEPS + t];
        }
        if (tid < JH) {
            smem[IK_OFF + tid]   = ik[jh0 + tid];
            smem[BTMK_OFF + tid] = d_BTmk[jh0 + tid];
            smem[HE_OFF + tid]   = he[jh0 + tid];
        }
        if (tid < JM) {
            smem[BT_OFF + tid] = BT[jm0 + tid];
            smem[ME_OFF + tid] = me[jm0 + tid];
        }
        if (tid == 0) smem[IE_OFF] = ie[0];
    }
    __syncthreads();

    // ---- per-thread role constants ----
    const int w    = tid >> 5;
    const int lane = tid & 31;
    const int sh   = w >> 1;          // k-slice 0..3
    const int csh  = w & 1;           // column half 0..1
    const int bp   = lane >> 3;       // batch pair 0..3
    const int c    = lane & 7;
    const int colA = csh * 16 + c;    // h columns (local 0..31)
    const int colB = colA + 8;
    const int colM = csh * 8 + c;     // m column (local 0..15)

    // core pointers (ulonglong2 == float4 == 16 bytes; index strides below are
    // in 16-byte units: WHK/WMK rows are 32 float4 wide, WAT rows 16 float4)
    const ulonglong2* pHA = reinterpret_cast<const ulonglong2*>(HS4w + (2*bp  ) * 129 + sh * 32);
    const ulonglong2* pHB = reinterpret_cast<const ulonglong2*>(HS4w + (2*bp+1) * 129 + sh * 32);
    const ulonglong2* pMA = reinterpret_cast<const ulonglong2*>(MS4w + (2*bp  ) * 65  + sh * 16);
    const ulonglong2* pMB = reinterpret_cast<const ulonglong2*>(MS4w + (2*bp+1) * 65  + sh * 16);
    const ulonglong2* pWA  = reinterpret_cast<const ulonglong2*>(WHK4 + sh * 32 * 32 + colA);
    const ulonglong2* pWB  = reinterpret_cast<const ulonglong2*>(WHK4 + sh * 32 * 32 + colB);
    const ulonglong2* pW2A = reinterpret_cast<const ulonglong2*>(WMK4 + sh * 16 * 32 + colA);
    const ulonglong2* pW2B = reinterpret_cast<const ulonglong2*>(WMK4 + sh * 16 * 32 + colB);
    const ulonglong2* pWM  = reinterpret_cast<const ulonglong2*>(WAT4 + sh * 16 * 16 + colM);

    // epilogue roles
    const int eb = tid >> 5, ec = tid & 31;        // h-epilogue: (batch, col)
    const int mb = tid >> 4, mc = tid & 15;        // m-epilogue: (batch, col), tid<128

    for (int t = 0; t < TSTEPS; ++t) {
        const int p = t & 1;

        // ---- stage A: copy state from global into padded SMEM rows ----
        {
            const float4* hg = reinterpret_cast<const float4*>(d_hbuf[p] + b0 * UNITS);
            #pragma unroll
            for (int i = tid; i < BPG * UNITS / 4; i += NTHREADS)
                HS4w[(i >> 7) * 129 + (i & 127)] = __ldcg(hg + i);
            const float4* mg = reinterpret_cast<const float4*>(d_mbuf[p] + b0 * ORDER);
            #pragma unroll
            for (int i = tid; i < BPG * ORDER / 4; i += NTHREADS)
                MS4w[(i >> 6) * 65 + (i & 63)] = __ldcg(mg + i);
        }
        // issue u-partial loads early (latency hides under core GEMM)
        float up[CPG];
        if (tid < BPG && t > 0) {
            const float* upp = d_upart + ((size_t)t * BATCH + b0 + tid) * CPG;
            #pragma unroll
            for (int q = 0; q < CPG; ++q) up[q] = __ldcg(upp + q);
        }
        __syncthreads();

        // ---- core GEMM: partials for h columns (hk + MK2) ----
        u64 a00=0, a01=0, a10=0, a11=0;   // colA: (batch even/odd) x (k-pair lo/hi)
        u64 e00=0, e01=0, e10=0, e11=0;   // colB
        #pragma unroll 8
        for (int i = 0; i < 32; ++i) {
            ulonglong2 hA = pHA[i], hB = pHB[i];
            ulonglong2 wA = pWA[i * 32], wB = pWB[i * 32];   // kc-row stride = 32 (16B units)
            fma2(a00, wA.x, hA.x); fma2(a01, wA.y, hA.y);
            fma2(a10, wA.x, hB.x); fma2(a11, wA.y, hB.y);
            fma2(e00, wB.x, hA.x); fma2(e01, wB.y, hA.y);
            fma2(e10, wB.x, hB.x); fma2(e11, wB.y, hB.y);
        }
        #pragma unroll 8
        for (int i = 0; i < 16; ++i) {
            ulonglong2 mA = pMA[i], mB = pMB[i];
            ulonglong2 wA = pW2A[i * 32], wB = pW2B[i * 32]; // kc-row stride = 32
            fma2(a00, wA.x, mA.x); fma2(a01, wA.y, mA.y);
            fma2(a10, wA.x, mB.x); fma2(a11, wA.y, mB.y);
            fma2(e00, wB.x, mA.x); fma2(e01, wB.y, mA.y);
            fma2(e10, wB.x, mB.x); fma2(e11, wB.y, mB.y);
        }
        {
            float* ph = smem + PH_OFF;
            ph[(sh*8 + 2*bp  )*33 + colA] = red2(a00) + red2(a01);
            ph[(sh*8 + 2*bp+1)*33 + colA] = red2(a10) + red2(a11);
            ph[(sh*8 + 2*bp  )*33 + colB] = red2(e00) + red2(e01);
            ph[(sh*8 + 2*bp+1)*33 + colB] = red2(e10) + red2(e11);
        }

        // ---- core GEMM: partials for m columns (AT) ----
        {
            u64 c00=0, c01=0, c10=0, c11=0;
            #pragma unroll 8
            for (int i = 0; i < 16; ++i) {
                ulonglong2 mA = pMA[i], mB = pMB[i];
                ulonglong2 wv = pWM[i * 16];                 // kc-row stride = 16
                fma2(c00, wv.x, mA.x); fma2(c01, wv.y, mA.y);
                fma2(c10, wv.x, mB.x); fma2(c11, wv.y, mB.y);
            }
            float* pm = smem + PM_OFF;
            pm[(sh*8 + 2*bp  )*17 + colM] = red2(c00) + red2(c01);
            pm[(sh*8 + 2*bp+1)*17 + colM] = red2(c10) + red2(c11);
        }

        // ---- u for this step (loads already in flight) ----
        if (tid < BPG) {
            float u = smem[XS_OFF + tid * TSTEPS + t] * smem[IE_OFF];
            if (t > 0) {
                #pragma unroll
                for (int q = 0; q < CPG; ++q) u += up[q];
            }
            smem[US_OFF + tid] = u;
        }
        __syncthreads();

        // ---- epilogue h: (batch eb, col ec) ----
        {
            const float* ph = smem + PH_OFF;
            float v = (ph[(0*8+eb)*33 + ec] + ph[(1*8+eb)*33 + ec])
                    + (ph[(2*8+eb)*33 + ec] + ph[(3*8+eb)*33 + ec]);
            v += smem[XS_OFF + eb * TSTEPS + t] * smem[IK_OFF + ec];
            v += smem[US_OFF + eb] * smem[BTMK_OFF + ec];
            float hv = tanhf(v);
            out[((size_t)(b0 + eb) * TSTEPS + t) * UNITS + jh0 + ec] = hv;
            __stcg(&d_hbuf[p ^ 1][(b0 + eb) * UNITS + jh0 + ec], hv);
            float hw = smem[HE_OFF + ec] * hv;
            hw += __shfl_down_sync(0xffffffffu, hw, 16);
            hw += __shfl_down_sync(0xffffffffu, hw, 8);
            hw += __shfl_down_sync(0xffffffffu, hw, 4);
            hw += __shfl_down_sync(0xffffffffu, hw, 2);
            hw += __shfl_down_sync(0xffffffffu, hw, 1);
            if (ec == 0) smem[HEP_OFF + eb] = hw;
        }

        // ---- epilogue m: (batch mb, col mc), tid<128 ----
        if (tid < 128) {
            const float* pm = smem + PM_OFF;
            float dot = (pm[(0*8+mb)*17 + mc] + pm[(1*8+mb)*17 + mc])
                      + (pm[(2*8+mb)*17 + mc] + pm[(3*8+mb)*17 + mc]);
            float mold = smem[MS_OFF + mb * 260 + jm0 + mc];
            float mnew = mold + dot + smem[US_OFF + mb] * smem[BT_OFF + mc];
            __stcg(&d_mbuf[p ^ 1][(b0 + mb) * ORDER + jm0 + mc], mnew);
            float mw = smem[ME_OFF + mc] * mnew;
            mw += __shfl_down_sync(0xffffffffu, mw, 8, 16);
            mw += __shfl_down_sync(0xffffffffu, mw, 4, 16);
            mw += __shfl_down_sync(0xffffffffu, mw, 2, 16);
            mw += __shfl_down_sync(0xffffffffu, mw, 1, 16);
            if (mc == 0) smem[MEP_OFF + mb] = mw;
        }
        __syncthreads();

        if (tid < BPG)
            d_upart[((size_t)(t + 1) * BATCH + b0 + tid) * CPG + cg] =
                smem[HEP_OFF + tid] + smem[MEP_OFF + tid];

        __threadfence();
        __syncthreads();

        // ---- 16-CTA group barrier ----
        if (tid == 0) {
            unsigned target = (unsigned)(t + 1);
            if (atomicAdd(&d_bar_count[g], 1u) == CPG - 1) {
                d_bar_count[g] = 0;
                __threadfence();
                d_bar_gen[g] = target;
            } else {
                while (d_bar_gen[g] < target) { }
            }
            __threadfence();
        }
        __syncthreads();
    }
}

// ===================== launch =====================
extern "C" void kernel_launch(void* const* d_in, const int* in_sizes, int n_in,
                              void* d_out, int out_size) {
    const float* x  = (const float*)d_in[0];
    const float* ie = (const float*)d_in[1];
    const float* he = (const float*)d_in[2];
    const float* me = (const float*)d_in[3];
    const float* ik = (const float*)d_in[4];
    const float* hk = (const float*)d_in[5];
    const float* mk = (const float*)d_in[6];
    const float* AT = (const float*)d_in[7];
    const float* BT = (const float*)d_in[8];
    float* out = (float*)d_out;

    cudaFuncSetAttribute(lmu_main_kernel,
                         cudaFuncAttributeMaxDynamicSharedMemorySize, SMEM_BYTES);

    lmu_setup_kernel<<<520, 256>>>(mk, AT, BT);
    lmu_main_kernel<<<NCTA, NTHREADS, SMEM_BYTES>>>(x, ie, he, me, ik, hk, AT, BT, out);
}

// round 11
// speedup vs baseline: 1.5078x; 1.0231x over previous
#include <cuda_runtime.h>
#include <math.h>

#define UNITS   512
#define ORDER   256
#define TSTEPS  1024
#define BATCH   64

#define NCTA     128
#define NTHREADS 512
#define GROUPS   8
#define CPG      16   // CTAs per group
#define BPG      8    // batches per group
#define JH       32   // h columns per CTA
#define JM       16   // m columns per CTA

// ---- shared memory layout (float offsets) ----
#define WHK_OFF   0        // [128 kc][32 col] float4 = 16384 f
#define WMK_OFF   16384    // [64 kc][32 col] float4 =  8192 f
#define WAT_OFF   24576    // [64 kc][16 col] float4 =  4096 f
#define HS_OFF    28672    // 8 rows, stride 129 float4 (516 floats) = 4128 f
#define MS_OFF    32800    // 8 rows, stride 65 float4 (260 floats)  = 2080 f
#define XS_OFF    34880    // [8][1024] = 8192 f
#define PH_OFF    43072    // [8 slices][8 batch][33] = 2112 f
#define PM_OFF    45184    // [8 slices][8 batch][17] = 1088 f
#define IK_OFF    46272
#define BTMK_OFF  46304
#define HE_OFF    46336
#define BT_OFF    46368
#define ME_OFF    46384
#define US_OFF    46400
#define HEP_OFF   46408
#define MEP_OFF   46416
#define IE_OFF    46424
#define SMEM_FLOATS 46428
#define SMEM_BYTES  (SMEM_FLOATS * 4)

// ---- device scratch ----
__device__ float d_MK2[ORDER * UNITS];                 // mk + AT@mk
__device__ float d_BTmk[UNITS];                        // BT@mk
__device__ float d_hbuf[2][BATCH * UNITS];             // double-buffered h state
__device__ float d_mbuf[2][BATCH * ORDER];             // double-buffered m state
__device__ float d_upart[(TSTEPS + 1) * BATCH * CPG];  // per-CTA partials of h.he + m.me
__device__ unsigned int d_bar_count[GROUPS];
__device__ volatile unsigned int d_bar_gen[GROUPS];

typedef unsigned long long u64;

__device__ __forceinline__ void fma2(u64 &acc, u64 a, u64 b) {
    asm("fma.rn.f32x2 %0, %1, %2, %0;" : "+l"(acc) : "l"(a), "l"(b));
}
__device__ __forceinline__ float red2(u64 v) {
    float lo, hi;
    asm("mov.b64 {%0, %1}, %2;" : "=f"(lo), "=f"(hi) : "l"(v));
    return lo + hi;
}

// ===================== setup =====================
__global__ void lmu_setup_kernel(const float* __restrict__ mk,
                                 const float* __restrict__ AT,
                                 const float* __restrict__ BT) {
    int blk = blockIdx.x, tid = threadIdx.x;
    if (blk < 512) {
        int e = blk * 256 + tid;
        int k = e >> 9, j = e & 511;
        float acc = mk[k * UNITS + j];
        const float* atrow = AT + k * ORDER;
        #pragma unroll 4
        for (int q = 0; q < ORDER; ++q) acc += atrow[q] * mk[q * UNITS + j];
        d_MK2[e] = acc;
    } else if (blk == 512) {
        for (int j = tid; j < UNITS; j += 256) {
            float acc = 0.f;
            #pragma unroll 4
            for (int q = 0; q < ORDER; ++q) acc += BT[q] * mk[q * UNITS + j];
            d_BTmk[j] = acc;
        }
    } else if (blk <= 518) {
        int base = (blk - 513) * 256 + tid;
        for (int i = base; i < BATCH * UNITS; i += 6 * 256) d_hbuf[0][i] = 0.f;
        for (int i = base; i < BATCH * ORDER; i += 6 * 256) d_mbuf[0][i] = 0.f;
    } else {
        if (tid < GROUPS) { d_bar_count[tid] = 0; d_bar_gen[tid] = 0; }
    }
}

// ===================== main persistent kernel =====================
extern __shared__ float smem[];

__global__ void __launch_bounds__(NTHREADS, 1)
lmu_main_kernel(const float* __restrict__ x,    // [64,1024,1]
                const float* __restrict__ ie,   // [1,1]
                const float* __restrict__ he,   // [512,1]
                const float* __restrict__ me,   // [256,1]
                const float* __restrict__ ik,   // [1,512]
                const float* __restrict__ hk,   // [512,512]
                const float* __restrict__ AT,   // [256,256]
                const float* __restrict__ BT,   // [1,256]
                float* __restrict__ out)        // [64,1024,512]
{
    const int tid = threadIdx.x;
    const int g   = blockIdx.x >> 4;     // group 0..7
    const int cg  = blockIdx.x & 15;     // CTA within group
    const int b0  = g * BPG;
    const int jh0 = cg * JH;
    const int jm0 = cg * JM;

    float4*       HS4w  = reinterpret_cast<float4*>(smem + HS_OFF);
    float4*       MS4w  = reinterpret_cast<float4*>(smem + MS_OFF);
    const float4* WHK4  = reinterpret_cast<const float4*>(smem + WHK_OFF);
    const float4* WMK4  = reinterpret_cast<const float4*>(smem + WMK_OFF);
    const float4* WAT4  = reinterpret_cast<const float4*>(smem + WAT_OFF);

    // ---- one-time weight preload (transposed into [kc][col] float4 tiles) ----
    {
        float4* w = reinterpret_cast<float4*>(smem + WHK_OFF);
        for (int idx = tid; idx < 128 * 32; idx += NTHREADS) {
            int kc = idx >> 5, col = idx & 31;
            int k = kc * 4, j = jh0 + col;
            w[idx] = make_float4(hk[(k+0)*UNITS + j], hk[(k+1)*UNITS + j],
                                 hk[(k+2)*UNITS + j], hk[(k+3)*UNITS + j]);
        }
        float4* w2 = reinterpret_cast<float4*>(smem + WMK_OFF);
        for (int idx = tid; idx < 64 * 32; idx += NTHREADS) {
            int kc = idx >> 5, col = idx & 31;
            int k = kc * 4, j = jh0 + col;
            w2[idx] = make_float4(d_MK2[(k+0)*UNITS + j], d_MK2[(k+1)*UNITS + j],
                                  d_MK2[(k+2)*UNITS + j], d_MK2[(k+3)*UNITS + j]);
        }
        float4* w3 = reinterpret_cast<float4*>(smem + WAT_OFF);
        for (int idx = tid; idx < 64 * 16; idx += NTHREADS) {
            int kc = idx >> 4, col = idx & 15;
            int k = kc * 4, j = jm0 + col;
            w3[idx] = make_float4(AT[(k+0)*ORDER + j], AT[(k+1)*ORDER + j],
                                  AT[(k+2)*ORDER + j], AT[(k+3)*ORDER + j]);
        }
        // x preload: xs[b][t]
        for (int i = tid; i < BPG * TSTEPS; i += NTHREADS) {
            int b = i >> 10, t = i & 1023;
            smem[XS_OFF + i] = x[(b0 + b) * TSTEPS + t];
        }
        if (tid < JH) {
            smem[IK_OFF + tid]   = ik[jh0 + tid];
            smem[BTMK_OFF + tid] = d_BTmk[jh0 + tid];
            smem[HE_OFF + tid]   = he[jh0 + tid];
        }
        if (tid < JM) {
            smem[BT_OFF + tid] = BT[jm0 + tid];
            smem[ME_OFF + tid] = me[jm0 + tid];
        }
        if (tid == 0) smem[IE_OFF] = ie[0];
    }
    __syncthreads();

    // ---- per-thread role constants ----
    const int w    = tid >> 5;        // warp 0..15
    const int lane = tid & 31;
    const int sh   = w >> 1;          // k-slice 0..7
    const int csh  = w & 1;           // column half 0..1
    const int bp   = lane >> 3;       // batch pair 0..3
    const int c    = lane & 7;
    const int colA = csh * 16 + c;    // h columns (local 0..31)
    const int colB = colA + 8;
    const int colM = csh * 8 + c;     // m column (local 0..15)

    // core pointers (ulonglong2 == float4 == 16 bytes; strides in 16B units)
    const ulonglong2* pHA = reinterpret_cast<const ulonglong2*>(HS4w + (2*bp  ) * 129 + sh * 16);
    const ulonglong2* pHB = reinterpret_cast<const ulonglong2*>(HS4w + (2*bp+1) * 129 + sh * 16);
    const ulonglong2* pMA = reinterpret_cast<const ulonglong2*>(MS4w + (2*bp  ) * 65  + sh * 8);
    const ulonglong2* pMB = reinterpret_cast<const ulonglong2*>(MS4w + (2*bp+1) * 65  + sh * 8);
    const ulonglong2* pWA  = reinterpret_cast<const ulonglong2*>(WHK4 + sh * 16 * 32 + colA);
    const ulonglong2* pWB  = reinterpret_cast<const ulonglong2*>(WHK4 + sh * 16 * 32 + colB);
    const ulonglong2* pW2A = reinterpret_cast<const ulonglong2*>(WMK4 + sh * 8 * 32 + colA);
    const ulonglong2* pW2B = reinterpret_cast<const ulonglong2*>(WMK4 + sh * 8 * 32 + colB);
    const ulonglong2* pWM  = reinterpret_cast<const ulonglong2*>(WAT4 + sh * 8 * 16 + colM);

    // epilogue roles
    const int eb = tid >> 5, ec = tid & 31;               // h-epilogue: warps 0-7
    const int mt = tid & 127, mb = mt >> 4, mc = mt & 15; // m-epilogue: warps 8-11
    const int ub = (tid - 384) >> 4, uq = tid & 15;       // u-reduce: warps 12-15

    for (int t = 0; t < TSTEPS; ++t) {
        const int p = t & 1;

        // ---- stage A: copy state from global into padded SMEM rows ----
        {
            const float4* hg = reinterpret_cast<const float4*>(d_hbuf[p] + b0 * UNITS);
            #pragma unroll
            for (int i = tid; i < BPG * UNITS / 4; i += NTHREADS)
                HS4w[(i >> 7) * 129 + (i & 127)] = __ldcg(hg + i);
            const float4* mg = reinterpret_cast<const float4*>(d_mbuf[p] + b0 * ORDER);
            #pragma unroll
            for (int i = tid; i < BPG * ORDER / 4; i += NTHREADS)
                MS4w[(i >> 6) * 65 + (i & 63)] = __ldcg(mg + i);
        }
        // u-partial load: warps 12-15, one element each; in flight through GEMM
        float upv = 0.f;
        if (tid >= 384 && t > 0)
            upv = __ldcg(d_upart + ((size_t)t * BATCH + b0 + ub) * CPG + uq);
        __syncthreads();

        // ---- core GEMM: partials for h columns (hk), 64 k per warp ----
        u64 a00=0, a01=0, a10=0, a11=0;   // colA: (batch even/odd) x (k-pair lo/hi)
        u64 e00=0, e01=0, e10=0, e11=0;   // colB
        #pragma unroll 4
        for (int i = 0; i < 16; ++i) {
            ulonglong2 hA = pHA[i], hB = pHB[i];
            ulonglong2 wA = pWA[i * 32], wB = pWB[i * 32];   // kc-row stride = 32 (16B units)
            fma2(a00, wA.x, hA.x); fma2(a01, wA.y, hA.y);
            fma2(a10, wA.x, hB.x); fma2(a11, wA.y, hB.y);
            fma2(e00, wB.x, hA.x); fma2(e01, wB.y, hA.y);
            fma2(e10, wB.x, hB.x); fma2(e11, wB.y, hB.y);
        }
        // ---- merged m loop: MK2 (into h accums) + AT (into m accums), 32 k ----
        u64 c00=0, c01=0, c10=0, c11=0;
        #pragma unroll 4
        for (int i = 0; i < 8; ++i) {
            ulonglong2 mA = pMA[i], mB = pMB[i];
            ulonglong2 wA = pW2A[i * 32], wB = pW2B[i * 32]; // kc-row stride = 32
            ulonglong2 wv = pWM[i * 16];                     // kc-row stride = 16
            fma2(a00, wA.x, mA.x); fma2(a01, wA.y, mA.y);
            fma2(a10, wA.x, mB.x); fma2(a11, wA.y, mB.y);
            fma2(e00, wB.x, mA.x); fma2(e01, wB.y, mA.y);
            fma2(e10, wB.x, mB.x); fma2(e11, wB.y, mB.y);
            fma2(c00, wv.x, mA.x); fma2(c01, wv.y, mA.y);
            fma2(c10, wv.x, mB.x); fma2(c11, wv.y, mB.y);
        }
        {
            float* ph = smem + PH_OFF;
            ph[(sh*8 + 2*bp  )*33 + colA] = red2(a00) + red2(a01);
            ph[(sh*8 + 2*bp+1)*33 + colA] = red2(a10) + red2(a11);
            ph[(sh*8 + 2*bp  )*33 + colB] = red2(e00) + red2(e01);
            ph[(sh*8 + 2*bp+1)*33 + colB] = red2(e10) + red2(e11);
            float* pm = smem + PM_OFF;
            pm[(sh*8 + 2*bp  )*17 + colM] = red2(c00) + red2(c01);
            pm[(sh*8 + 2*bp+1)*17 + colM] = red2(c10) + red2(c11);
        }

        // ---- u for this step: warps 12-15 reduce the in-flight partials ----
        if (tid >= 384) {
            upv += __shfl_down_sync(0xffffffffu, upv, 8, 16);
            upv += __shfl_down_sync(0xffffffffu, upv, 4, 16);
            upv += __shfl_down_sync(0xffffffffu, upv, 2, 16);
            upv += __shfl_down_sync(0xffffffffu, upv, 1, 16);
            if (uq == 0)
                smem[US_OFF + ub] = upv + smem[XS_OFF + ub * TSTEPS + t] * smem[IE_OFF];
        }
        __syncthreads();

        // ---- epilogue h: warps 0-7, (batch eb, col ec) ----
        if (tid < 256) {
            const float* ph = smem + PH_OFF;
            float v = ((ph[(0*8+eb)*33 + ec] + ph[(1*8+eb)*33 + ec])
                     + (ph[(2*8+eb)*33 + ec] + ph[(3*8+eb)*33 + ec]))
                    + ((ph[(4*8+eb)*33 + ec] + ph[(5*8+eb)*33 + ec])
                     + (ph[(6*8+eb)*33 + ec] + ph[(7*8+eb)*33 + ec]));
            v += smem[XS_OFF + eb * TSTEPS + t] * smem[IK_OFF + ec];
            v += smem[US_OFF + eb] * smem[BTMK_OFF + ec];
            float hv = tanhf(v);
            out[((size_t)(b0 + eb) * TSTEPS + t) * UNITS + jh0 + ec] = hv;
            __stcg(&d_hbuf[p ^ 1][(b0 + eb) * UNITS + jh0 + ec], hv);
            float hw = smem[HE_OFF + ec] * hv;
            hw += __shfl_down_sync(0xffffffffu, hw, 16);
            hw += __shfl_down_sync(0xffffffffu, hw, 8);
            hw += __shfl_down_sync(0xffffffffu, hw, 4);
            hw += __shfl_down_sync(0xffffffffu, hw, 2);
            hw += __shfl_down_sync(0xffffffffu, hw, 1);
            if (ec == 0) smem[HEP_OFF + eb] = hw;
        } else if (tid < 384) {
            // ---- epilogue m: warps 8-11, (batch mb, col mc) ----
            const float* pm = smem + PM_OFF;
            float dot = ((pm[(0*8+mb)*17 + mc] + pm[(1*8+mb)*17 + mc])
                       + (pm[(2*8+mb)*17 + mc] + pm[(3*8+mb)*17 + mc]))
                      + ((pm[(4*8+mb)*17 + mc] + pm[(5*8+mb)*17 + mc])
                       + (pm[(6*8+mb)*17 + mc] + pm[(7*8+mb)*17 + mc]));
            float mold = smem[MS_OFF + mb * 260 + jm0 + mc];
            float mnew = mold + dot + smem[US_OFF + mb] * smem[BT_OFF + mc];
            __stcg(&d_mbuf[p ^ 1][(b0 + mb) * ORDER + jm0 + mc], mnew);
            float mw = smem[ME_OFF + mc] * mnew;
            mw += __shfl_down_sync(0xffffffffu, mw, 8, 16);
            mw += __shfl_down_sync(0xffffffffu, mw, 4, 16);
            mw += __shfl_down_sync(0xffffffffu, mw, 2, 16);
            mw += __shfl_down_sync(0xffffffffu, mw, 1, 16);
            if (mc == 0) smem[MEP_OFF + mb] = mw;
        }
        __syncthreads();

        if (tid < BPG)
            d_upart[((size_t)(t + 1) * BATCH + b0 + tid) * CPG + cg] =
                smem[HEP_OFF + tid] + smem[MEP_OFF + tid];

        __threadfence();
        __syncthreads();

        // ---- 16-CTA group barrier ----
        if (tid == 0) {
            unsigned target = (unsigned)(t + 1);
            if (atomicAdd(&d_bar_count[g], 1u) == CPG - 1) {
                d_bar_count[g] = 0;
                __threadfence();
                d_bar_gen[g] = target;
            } else {
                while (d_bar_gen[g] < target) { }
            }
            __threadfence();
        }
        __syncthreads();
    }
}

// ===================== launch =====================
extern "C" void kernel_launch(void* const* d_in, const int* in_sizes, int n_in,
                              void* d_out, int out_size) {
    const float* x  = (const float*)d_in[0];
    const float* ie = (const float*)d_in[1];
    const float* he = (const float*)d_in[2];
    const float* me = (const float*)d_in[3];
    const float* ik = (const float*)d_in[4];
    const float* hk = (const float*)d_in[5];
    const float* mk = (const float*)d_in[6];
    const float* AT = (const float*)d_in[7];
    const float* BT = (const float*)d_in[8];
    float* out = (float*)d_out;

    cudaFuncSetAttribute(lmu_main_kernel,
                         cudaFuncAttributeMaxDynamicSharedMemorySize, SMEM_BYTES);

    lmu_setup_kernel<<<520, 256>>>(mk, AT, BT);
    lmu_main_kernel<<<NCTA, NTHREADS, SMEM_BYTES>>>(x, ie, he, me, ik, hk, AT, BT, out);
}